// round 5
// baseline (speedup 1.0000x reference)
#include <cuda_runtime.h>
#include <cuda_bf16.h>
#include <cstdint>
#include <math.h>

#define B_   16
#define S_   2048
#define D_   128
#define H_   4
#define DH_  32
#define FF_  512
#define L_   4
#define OUT_ 30
#define M_   (B_*S_)   // 32768

// log2(e) / sqrt(32): folded into Q so softmax is a bare ex2
#define QSCALE 0.25506626866f

// ======================= low-level helpers =======================
__device__ __forceinline__ void mma16816(float* d, const uint32_t* a, const uint32_t* b) {
    asm volatile("mma.sync.aligned.m16n8k16.row.col.f32.bf16.bf16.f32 "
        "{%0,%1,%2,%3}, {%4,%5,%6,%7}, {%8,%9}, {%0,%1,%2,%3};"
        : "+f"(d[0]), "+f"(d[1]), "+f"(d[2]), "+f"(d[3])
        : "r"(a[0]), "r"(a[1]), "r"(a[2]), "r"(a[3]), "r"(b[0]), "r"(b[1]));
}
__device__ __forceinline__ uint32_t packbf2(float x, float y) {
    __nv_bfloat162 p = __floats2bfloat162_rn(x, y);
    return *(uint32_t*)&p;
}
__device__ __forceinline__ float ex2f(float x) {
    float y; asm("ex2.approx.f32 %0, %1;" : "=f"(y) : "f"(x)); return y;
}
__device__ __forceinline__ uint32_t cvta_s(const void* p) {
    return (uint32_t)__cvta_generic_to_shared(p);
}
__device__ __forceinline__ void cp16(uint32_t dst, const void* src) {
    asm volatile("cp.async.cg.shared.global [%0], [%1], 16;" :: "r"(dst), "l"(src));
}
#define CP_COMMIT() asm volatile("cp.async.commit_group;" ::: "memory")
#define CP_WAIT(n)  asm volatile("cp.async.wait_group %0;" :: "n"(n) : "memory")
__device__ __forceinline__ void ldm_x4(uint32_t* r, uint32_t a) {
    asm volatile("ldmatrix.sync.aligned.m8n8.x4.shared.b16 {%0,%1,%2,%3}, [%4];"
        : "=r"(r[0]), "=r"(r[1]), "=r"(r[2]), "=r"(r[3]) : "r"(a));
}
__device__ __forceinline__ void ldm_x4t(uint32_t* r, uint32_t a) {
    asm volatile("ldmatrix.sync.aligned.m8n8.x4.trans.shared.b16 {%0,%1,%2,%3}, [%4];"
        : "=r"(r[0]), "=r"(r[1]), "=r"(r[2]), "=r"(r[3]) : "r"(a));
}

#define TST  40    // smem stride for 32-wide (k=32) bf16 tiles
#define TSTW 136   // smem stride for 128-wide bf16 tiles (16B rotation per row)

// ======================= scratch (device globals) =======================
__device__ __nv_bfloat16 g_qb[B_*H_*S_*DH_];
__device__ __nv_bfloat16 g_kb[B_*H_*S_*DH_];
__device__ __nv_bfloat16 g_vb[B_*H_*S_*DH_];
__device__ __nv_bfloat16 g_hb[M_*D_];
__device__ float         g_h[M_*D_];
__device__ __nv_bfloat16 g_wip[L_*3*D_*D_];
__device__ __nv_bfloat16 g_wout[L_*D_*D_];
__device__ __nv_bfloat16 g_wf1[L_*FF_*D_];
__device__ __nv_bfloat16 g_wf2[L_*D_*FF_];

// ======================= fp32 -> bf16 conversion =======================
__global__ __launch_bounds__(256) void cvt_kernel(const float* __restrict__ s,
                                                  __nv_bfloat16* __restrict__ d, int n) {
    int i = (blockIdx.x * 256 + threadIdx.x) * 4;
    if (i < n) {
        float4 v = *reinterpret_cast<const float4*>(s + i);
        *reinterpret_cast<uint2*>(d + i) = make_uint2(packbf2(v.x, v.y), packbf2(v.z, v.w));
    }
}

// ======================= QKV projection (bf16 MMA, pipelined) =======================
// C[128x128 tile] = hb @ Wqkv^T + bias -> scatter q/k/v [b,h,s,32]; q pre-scaled.
__global__ __launch_bounds__(256)
void qkv_kernel(const __nv_bfloat16* __restrict__ A, const __nv_bfloat16* __restrict__ W,
                const float* __restrict__ bias,
                __nv_bfloat16* __restrict__ qo, __nv_bfloat16* __restrict__ ko,
                __nv_bfloat16* __restrict__ vo)
{
    __shared__ __nv_bfloat16 As[2][128*TST];
    __shared__ __nv_bfloat16 Bs[2][128*TST];
    __shared__ float bias_s[128];

    const int t    = threadIdx.x;
    const int wid  = t >> 5;
    const int lane = t & 31;
    const int g    = lane >> 2;
    const int tq   = lane & 3;
    const int wm   = wid >> 2;
    const int wn   = wid & 3;
    const int row0 = blockIdx.y * 128;
    const int n0   = blockIdx.x * 128;
    const int K    = D_;

    if (t < 128) bias_s[t] = bias[n0 + t];

    const uint32_t sA[2] = { cvta_s(As[0]), cvta_s(As[1]) };
    const uint32_t sB[2] = { cvta_s(Bs[0]), cvta_s(Bs[1]) };

    auto load_tile = [&](int kt, int stg) {
        const int k0 = kt << 5;
#pragma unroll
        for (int i = 0; i < 2; i++) {
            int id = t + (i << 8);
            int r = id >> 2, qq = id & 3;
            cp16(sA[stg] + r * (TST*2) + qq * 16, &A[(size_t)(row0 + r) * K + k0 + qq * 8]);
            cp16(sB[stg] + r * (TST*2) + qq * 16, &W[(size_t)(n0   + r) * K + k0 + qq * 8]);
        }
    };

    float acc[4][4][4];
#pragma unroll
    for (int mf = 0; mf < 4; mf++)
#pragma unroll
        for (int nf = 0; nf < 4; nf++)
#pragma unroll
            for (int e = 0; e < 4; e++) acc[mf][nf][e] = 0.f;

    load_tile(0, 0);
    CP_COMMIT();

    const int aRow = wm * 64 + (lane & 15);
    const int aColX = (lane >> 4) * 8;
    const int bRow = wn * 32 + (lane & 7) + ((lane >> 4) << 3);
    const int bColX = ((lane >> 3) & 1) * 8;

    for (int kt = 0; kt < 4; kt++) {
        const int stg = kt & 1;
        if (kt + 1 < 4) { load_tile(kt + 1, stg ^ 1); CP_COMMIT(); CP_WAIT(1); }
        else CP_WAIT(0);
        __syncthreads();

#pragma unroll
        for (int ks = 0; ks < 2; ks++) {
            const int kk = ks << 4;
            uint32_t af[4][4];
#pragma unroll
            for (int mf = 0; mf < 4; mf++)
                ldm_x4(af[mf], sA[stg] + ((aRow + mf * 16) * TST + kk + aColX) * 2);
            uint32_t bf[4][2];
#pragma unroll
            for (int pp = 0; pp < 2; pp++) {
                uint32_t r4[4];
                ldm_x4(r4, sB[stg] + ((bRow + pp * 16) * TST + kk + bColX) * 2);
                bf[pp*2][0] = r4[0]; bf[pp*2][1] = r4[1];
                bf[pp*2+1][0] = r4[2]; bf[pp*2+1][1] = r4[3];
            }
#pragma unroll
            for (int mf = 0; mf < 4; mf++)
#pragma unroll
                for (int nf = 0; nf < 4; nf++)
                    mma16816(acc[mf][nf], af[mf], bf[nf]);
        }
        __syncthreads();
    }

#pragma unroll
    for (int mf = 0; mf < 4; mf++) {
        const int m0 = row0 + wm * 64 + mf * 16 + g;
        const int m1 = m0 + 8;
#pragma unroll
        for (int nf = 0; nf < 4; nf++) {
            const int c = wn * 32 + nf * 8 + tq * 2;
            float v0 = acc[mf][nf][0] + bias_s[c];
            float v1 = acc[mf][nf][1] + bias_s[c + 1];
            float v2 = acc[mf][nf][2] + bias_s[c];
            float v3 = acc[mf][nf][3] + bias_s[c + 1];
            __nv_bfloat16* dst = (blockIdx.x == 0) ? qo : ((blockIdx.x == 1) ? ko : vo);
            if (blockIdx.x == 0) { v0 *= QSCALE; v1 *= QSCALE; v2 *= QSCALE; v3 *= QSCALE; }
            const int hh = c >> 5, dd = c & 31;
            int b0i = m0 >> 11, s0i = m0 & 2047;
            int b1i = m1 >> 11, s1i = m1 & 2047;
            *reinterpret_cast<uint32_t*>(dst + ((size_t)(b0i * H_ + hh) * S_ + s0i) * DH_ + dd) = packbf2(v0, v1);
            *reinterpret_cast<uint32_t*>(dst + ((size_t)(b1i * H_ + hh) * S_ + s1i) * DH_ + dd) = packbf2(v2, v3);
        }
    }
}

// ======================= fused attention + out-proj + residual + LN1 =======================
// CTA: (b, 64-query block), 128 threads (4 warps x 16 queries). Heads 0..3 serial;
// per head: flash loop over 32 key-tiles of 64. Normalized O C-frags become out-proj
// A-frags directly (no memory). Out-proj vs Wo in smem, then residual+LN per row (quad).
#define AT_SMEM (5120 + 10240 + 10240 + 34816 + 1536)
__global__ __launch_bounds__(128)
void attn_fused_kernel(const __nv_bfloat16* __restrict__ q, const __nv_bfloat16* __restrict__ k,
                       const __nv_bfloat16* __restrict__ v, const __nv_bfloat16* __restrict__ Wo,
                       const float* __restrict__ ob, const float* __restrict__ R,
                       const float* __restrict__ lng, const float* __restrict__ lnb,
                       float* __restrict__ outF, __nv_bfloat16* __restrict__ outB)
{
    extern __shared__ char sm[];
    __nv_bfloat16* Qs  = (__nv_bfloat16*)(sm);
    __nv_bfloat16* Ks0 = (__nv_bfloat16*)(sm + 5120);
    __nv_bfloat16* Vs0 = (__nv_bfloat16*)(sm + 15360);
    __nv_bfloat16* Wos = (__nv_bfloat16*)(sm + 25600);
    float* bias_s = (float*)(sm + 60416);
    float* lng_s  = (float*)(sm + 60928);
    float* lnb_s  = (float*)(sm + 61440);

    const int t    = threadIdx.x;
    const int wid  = t >> 5;
    const int lane = t & 31;
    const int g    = lane >> 2;
    const int tq   = lane & 3;
    const int b    = blockIdx.y;
    const int q0   = blockIdx.x * 64;

    const uint32_t sQ = cvta_s(Qs);
    const uint32_t sK[2] = { cvta_s(Ks0), cvta_s(Ks0) + 5120 };
    const uint32_t sV[2] = { cvta_s(Vs0), cvta_s(Vs0) + 5120 };
    const uint32_t sWo = cvta_s(Wos);

    // stage Wo [128 n][128 k] (group A) + bias/ln params
#pragma unroll
    for (int i = 0; i < 16; i++) {
        int id = t + (i << 7);
        int r = id >> 4, cc = id & 15;
        cp16(sWo + (r * TSTW + cc * 8) * 2, &Wo[(size_t)r * 128 + cc * 8]);
    }
    if (t < 128) { bias_s[t] = ob[t]; lng_s[t] = lng[t]; lnb_s[t] = lnb[t]; }
    CP_COMMIT();

    // ldmatrix lane-offsets
    const int aRow = wid * 16 + (lane & 15);
    const int aColX = (lane >> 4) * 8;
    const int bRow = (lane & 7) + ((lane >> 4) << 3);
    const int bColX = ((lane >> 3) & 1) * 8;
    const int vRow = (lane & 7) + (((lane >> 3) & 1) << 3);
    const int vColX = (lane >> 4) * 8;

    uint32_t oa[8][4];   // out-proj A k-frags: [h*2+kf][4]

    for (int h = 0; h < H_; h++) {
        const int bh = b * H_ + h;
        // load Q_h (64x32) + KV tile 0 into stage 0
#pragma unroll
        for (int i = 0; i < 2; i++) {
            int id = t + (i << 7);
            int r = id >> 2, qq = id & 3;
            cp16(sQ + r * (TST*2) + qq * 16, &q[((size_t)bh * S_ + q0 + r) * DH_ + qq * 8]);
            cp16(sK[0] + r * (TST*2) + qq * 16, &k[((size_t)bh * S_ + r) * DH_ + qq * 8]);
            cp16(sV[0] + r * (TST*2) + qq * 16, &v[((size_t)bh * S_ + r) * DH_ + qq * 8]);
        }
        CP_COMMIT();

        float o4[4][4];
        float lg = 0.f, lg8 = 0.f;
#pragma unroll
        for (int nf = 0; nf < 4; nf++)
#pragma unroll
            for (int e = 0; e < 4; e++) o4[nf][e] = 0.f;
        uint32_t af2[2][4];

        for (int it = 0; it < (S_ >> 6); it++) {
            const int stg = it & 1;
            if (it + 1 < (S_ >> 6)) {
                const int j0 = (it + 1) << 6;
#pragma unroll
                for (int i = 0; i < 2; i++) {
                    int id = t + (i << 7);
                    int r = id >> 2, qq = id & 3;
                    cp16(sK[stg^1] + r * (TST*2) + qq * 16, &k[((size_t)bh * S_ + j0 + r) * DH_ + qq * 8]);
                    cp16(sV[stg^1] + r * (TST*2) + qq * 16, &v[((size_t)bh * S_ + j0 + r) * DH_ + qq * 8]);
                }
                CP_COMMIT(); CP_WAIT(1);
            } else CP_WAIT(0);
            __syncthreads();

            if (it == 0) {
#pragma unroll
                for (int ks = 0; ks < 2; ks++)
                    ldm_x4(af2[ks], sQ + (aRow * TST + ks * 16 + aColX) * 2);
            }

            // S = Q @ K^T
            float sc[8][4];
#pragma unroll
            for (int nf = 0; nf < 8; nf++)
#pragma unroll
                for (int e = 0; e < 4; e++) sc[nf][e] = 0.f;
#pragma unroll
            for (int ks = 0; ks < 2; ks++) {
                const int kk = ks << 4;
#pragma unroll
                for (int pp = 0; pp < 4; pp++) {
                    uint32_t r4[4];
                    ldm_x4(r4, sK[stg] + ((pp * 16 + bRow) * TST + kk + bColX) * 2);
                    uint32_t b0[2] = { r4[0], r4[1] }, b1[2] = { r4[2], r4[3] };
                    mma16816(sc[pp*2],   af2[ks], b0);
                    mma16816(sc[pp*2+1], af2[ks], b1);
                }
            }

            // p = ex2(s); accumulate l; pack P A-frags
            uint32_t pb[8][2];
#pragma unroll
            for (int nf = 0; nf < 8; nf++) {
                float p0 = ex2f(sc[nf][0]);
                float p1 = ex2f(sc[nf][1]);
                float p2 = ex2f(sc[nf][2]);
                float p3 = ex2f(sc[nf][3]);
                lg  += p0 + p1;
                lg8 += p2 + p3;
                pb[nf][0] = packbf2(p0, p1);
                pb[nf][1] = packbf2(p2, p3);
            }

            // O += P @ V
#pragma unroll
            for (int kf = 0; kf < 4; kf++) {
                uint32_t a4[4] = { pb[2*kf][0], pb[2*kf][1], pb[2*kf+1][0], pb[2*kf+1][1] };
#pragma unroll
                for (int pp = 0; pp < 2; pp++) {
                    uint32_t r4[4];
                    ldm_x4t(r4, sV[stg] + ((kf * 16 + vRow) * TST + pp * 16 + vColX) * 2);
                    uint32_t b0[2] = { r4[0], r4[1] }, b1[2] = { r4[2], r4[3] };
                    mma16816(o4[pp*2],   a4, b0);
                    mma16816(o4[pp*2+1], a4, b1);
                }
            }
            __syncthreads();
        }

        // normalize + pack O C-frags as out-proj A k-frags
        lg  += __shfl_xor_sync(0xffffffffu, lg, 1);
        lg  += __shfl_xor_sync(0xffffffffu, lg, 2);
        lg8 += __shfl_xor_sync(0xffffffffu, lg8, 1);
        lg8 += __shfl_xor_sync(0xffffffffu, lg8, 2);
        const float inv0 = 1.f / lg;
        const float inv1 = 1.f / lg8;
#pragma unroll
        for (int kf = 0; kf < 2; kf++) {
            oa[h*2+kf][0] = packbf2(o4[2*kf][0]   * inv0, o4[2*kf][1]   * inv0);
            oa[h*2+kf][1] = packbf2(o4[2*kf][2]   * inv1, o4[2*kf][3]   * inv1);
            oa[h*2+kf][2] = packbf2(o4[2*kf+1][0] * inv0, o4[2*kf+1][1] * inv0);
            oa[h*2+kf][3] = packbf2(o4[2*kf+1][2] * inv1, o4[2*kf+1][3] * inv1);
        }
    }

    // ---- out-projection: [64,128] @ Wo^T, from registers ----
    float acc2[16][4];
#pragma unroll
    for (int nf = 0; nf < 16; nf++)
#pragma unroll
        for (int e = 0; e < 4; e++) acc2[nf][e] = 0.f;
#pragma unroll
    for (int kf = 0; kf < 8; kf++) {
#pragma unroll
        for (int np = 0; np < 8; np++) {
            uint32_t r4[4];
            ldm_x4(r4, sWo + ((np * 16 + bRow) * TSTW + kf * 16 + bColX) * 2);
            uint32_t b0[2] = { r4[0], r4[1] }, b1[2] = { r4[2], r4[3] };
            mma16816(acc2[np*2],   oa[kf], b0);
            mma16816(acc2[np*2+1], oa[kf], b1);
        }
    }

    // ---- bias + residual + LayerNorm (warp owns full 128-wide rows) ----
    const int m0 = b * S_ + q0 + wid * 16 + g;
    const int m1 = m0 + 8;
    float s0 = 0.f, sq0 = 0.f, s1 = 0.f, sq1 = 0.f;
#pragma unroll
    for (int nf = 0; nf < 16; nf++) {
        const int c = nf * 8 + tq * 2;
        float2 r0 = *reinterpret_cast<const float2*>(R + (size_t)m0 * 128 + c);
        float2 r1 = *reinterpret_cast<const float2*>(R + (size_t)m1 * 128 + c);
        float v0 = acc2[nf][0] + bias_s[c]     + r0.x;
        float v1 = acc2[nf][1] + bias_s[c + 1] + r0.y;
        float v2 = acc2[nf][2] + bias_s[c]     + r1.x;
        float v3 = acc2[nf][3] + bias_s[c + 1] + r1.y;
        acc2[nf][0] = v0; acc2[nf][1] = v1; acc2[nf][2] = v2; acc2[nf][3] = v3;
        s0 += v0 + v1; sq0 += v0*v0 + v1*v1;
        s1 += v2 + v3; sq1 += v2*v2 + v3*v3;
    }
    s0  += __shfl_xor_sync(0xffffffffu, s0, 1);  s0  += __shfl_xor_sync(0xffffffffu, s0, 2);
    sq0 += __shfl_xor_sync(0xffffffffu, sq0, 1); sq0 += __shfl_xor_sync(0xffffffffu, sq0, 2);
    s1  += __shfl_xor_sync(0xffffffffu, s1, 1);  s1  += __shfl_xor_sync(0xffffffffu, s1, 2);
    sq1 += __shfl_xor_sync(0xffffffffu, sq1, 1); sq1 += __shfl_xor_sync(0xffffffffu, sq1, 2);
    float mean0 = s0 * (1.f/128.f);
    float mean1 = s1 * (1.f/128.f);
    float rstd0 = rsqrtf(sq0 * (1.f/128.f) - mean0*mean0 + 1e-5f);
    float rstd1 = rsqrtf(sq1 * (1.f/128.f) - mean1*mean1 + 1e-5f);
#pragma unroll
    for (int nf = 0; nf < 16; nf++) {
        const int c = nf * 8 + tq * 2;
        float y0 = (acc2[nf][0] - mean0) * rstd0 * lng_s[c]   + lnb_s[c];
        float y1 = (acc2[nf][1] - mean0) * rstd0 * lng_s[c+1] + lnb_s[c+1];
        float y2 = (acc2[nf][2] - mean1) * rstd1 * lng_s[c]   + lnb_s[c];
        float y3 = (acc2[nf][3] - mean1) * rstd1 * lng_s[c+1] + lnb_s[c+1];
        *reinterpret_cast<float2*>(outF + (size_t)m0 * 128 + c) = make_float2(y0, y1);
        *reinterpret_cast<float2*>(outF + (size_t)m1 * 128 + c) = make_float2(y2, y3);
        *reinterpret_cast<uint32_t*>(outB + (size_t)m0 * 128 + c) = packbf2(y0, y1);
        *reinterpret_cast<uint32_t*>(outB + (size_t)m1 * 128 + c) = packbf2(y2, y3);
    }
}

// ======================= fused FFN: relu(A@W1^T+b1)@W2^T + b2 + residual + LN2 =======================
// CTA = 64 rows, 128 threads (4 warps x 16 rows). FF streamed in 4 chunks of 128;
// T C-frags repack directly as GEMM2 A-frags (no smem round trip).
#define FF_SMEM (17408 + 34816 + 34816 + 2048 + 1536)
__global__ __launch_bounds__(128)
void ffn_kernel(const __nv_bfloat16* __restrict__ Ain,
                const __nv_bfloat16* __restrict__ W1, const float* __restrict__ b1,
                const __nv_bfloat16* __restrict__ W2, const float* __restrict__ b2,
                const float* __restrict__ R, const float* __restrict__ lng,
                const float* __restrict__ lnb,
                float* __restrict__ outF, __nv_bfloat16* __restrict__ outB)
{
    extern __shared__ char sm[];
    __nv_bfloat16* As  = (__nv_bfloat16*)(sm);
    __nv_bfloat16* W1s = (__nv_bfloat16*)(sm + 17408);
    __nv_bfloat16* W2s = (__nv_bfloat16*)(sm + 52224);
    float* b1s  = (float*)(sm + 87040);
    float* b2s  = (float*)(sm + 89088);
    float* lng_s = (float*)(sm + 89600);
    float* lnb_s = (float*)(sm + 90112);

    const int t    = threadIdx.x;
    const int wid  = t >> 5;
    const int lane = t & 31;
    const int g    = lane >> 2;
    const int tq   = lane & 3;
    const int row0 = blockIdx.x * 64;

    const uint32_t sA  = cvta_s(As);
    const uint32_t sW1 = cvta_s(W1s);
    const uint32_t sW2 = cvta_s(W2s);

    auto loadW = [&](int c) {
#pragma unroll
        for (int i = 0; i < 16; i++) {
            int id = t + (i << 7);
            int r = id >> 4, cc = id & 15;
            cp16(sW1 + (r * TSTW + cc * 8) * 2, &W1[(size_t)(c * 128 + r) * 128 + cc * 8]);
            cp16(sW2 + (r * TSTW + cc * 8) * 2, &W2[(size_t)r * 512 + c * 128 + cc * 8]);
        }
    };

    // A tile (64 x 128) + first W chunk
#pragma unroll
    for (int i = 0; i < 8; i++) {
        int id = t + (i << 7);
        int r = id >> 4, cc = id & 15;
        cp16(sA + (r * TSTW + cc * 8) * 2, &Ain[(size_t)(row0 + r) * 128 + cc * 8]);
    }
    loadW(0);
#pragma unroll
    for (int i = 0; i < 4; i++) b1s[t + (i << 7)] = b1[t + (i << 7)];
    if (t < 128) { b2s[t] = b2[t]; lng_s[t] = lng[t]; lnb_s[t] = lnb[t]; }
    CP_COMMIT();
    CP_WAIT(0);
    __syncthreads();

    const int aRow = wid * 16 + (lane & 15);
    const int aColX = (lane >> 4) * 8;
    const int bRow = (lane & 7) + ((lane >> 4) << 3);
    const int bColX = ((lane >> 3) & 1) * 8;

    // hoist A fragments (k=128 -> 8 k-frags)
    uint32_t afA[8][4];
#pragma unroll
    for (int kf = 0; kf < 8; kf++)
        ldm_x4(afA[kf], sA + (aRow * TSTW + kf * 16 + aColX) * 2);

    float acc2[16][4];
#pragma unroll
    for (int nf = 0; nf < 16; nf++)
#pragma unroll
        for (int e = 0; e < 4; e++) acc2[nf][e] = 0.f;

    for (int c = 0; c < 4; c++) {
        // GEMM1: T = A @ W1chunk^T  (n = 128 ff cols)
        float acc1[16][4];
#pragma unroll
        for (int nf = 0; nf < 16; nf++)
#pragma unroll
            for (int e = 0; e < 4; e++) acc1[nf][e] = 0.f;
#pragma unroll
        for (int kf = 0; kf < 8; kf++) {
#pragma unroll
            for (int np = 0; np < 8; np++) {
                uint32_t r4[4];
                ldm_x4(r4, sW1 + ((np * 16 + bRow) * TSTW + kf * 16 + bColX) * 2);
                uint32_t b0[2] = { r4[0], r4[1] }, b1f[2] = { r4[2], r4[3] };
                mma16816(acc1[np*2],   afA[kf], b0);
                mma16816(acc1[np*2+1], afA[kf], b1f);
            }
        }
        // relu + bias -> GEMM2 A k-frags
        uint32_t a1[8][4];
#pragma unroll
        for (int nf = 0; nf < 16; nf++) {
            const int col = c * 128 + nf * 8 + tq * 2;
            float v0 = fmaxf(acc1[nf][0] + b1s[col],     0.f);
            float v1 = fmaxf(acc1[nf][1] + b1s[col + 1], 0.f);
            float v2 = fmaxf(acc1[nf][2] + b1s[col],     0.f);
            float v3 = fmaxf(acc1[nf][3] + b1s[col + 1], 0.f);
            const int kf2 = nf >> 1;
            if ((nf & 1) == 0) { a1[kf2][0] = packbf2(v0, v1); a1[kf2][1] = packbf2(v2, v3); }
            else               { a1[kf2][2] = packbf2(v0, v1); a1[kf2][3] = packbf2(v2, v3); }
        }
        // GEMM2: acc2 += T @ W2chunk^T
#pragma unroll
        for (int kf = 0; kf < 8; kf++) {
#pragma unroll
            for (int np = 0; np < 8; np++) {
                uint32_t r4[4];
                ldm_x4(r4, sW2 + ((np * 16 + bRow) * TSTW + kf * 16 + bColX) * 2);
                uint32_t b0[2] = { r4[0], r4[1] }, b1f[2] = { r4[2], r4[3] };
                mma16816(acc2[np*2],   a1[kf], b0);
                mma16816(acc2[np*2+1], a1[kf], b1f);
            }
        }
        __syncthreads();
        if (c < 3) {
            loadW(c + 1);
            CP_COMMIT(); CP_WAIT(0);
            __syncthreads();
        }
    }

    // ---- bias + residual + LayerNorm ----
    const int m0 = row0 + wid * 16 + g;
    const int m1 = m0 + 8;
    float s0 = 0.f, sq0 = 0.f, s1 = 0.f, sq1 = 0.f;
#pragma unroll
    for (int nf = 0; nf < 16; nf++) {
        const int cc = nf * 8 + tq * 2;
        float2 r0 = *reinterpret_cast<const float2*>(R + (size_t)m0 * 128 + cc);
        float2 r1 = *reinterpret_cast<const float2*>(R + (size_t)m1 * 128 + cc);
        float v0 = acc2[nf][0] + b2s[cc]     + r0.x;
        float v1 = acc2[nf][1] + b2s[cc + 1] + r0.y;
        float v2 = acc2[nf][2] + b2s[cc]     + r1.x;
        float v3 = acc2[nf][3] + b2s[cc + 1] + r1.y;
        acc2[nf][0] = v0; acc2[nf][1] = v1; acc2[nf][2] = v2; acc2[nf][3] = v3;
        s0 += v0 + v1; sq0 += v0*v0 + v1*v1;
        s1 += v2 + v3; sq1 += v2*v2 + v3*v3;
    }
    s0  += __shfl_xor_sync(0xffffffffu, s0, 1);  s0  += __shfl_xor_sync(0xffffffffu, s0, 2);
    sq0 += __shfl_xor_sync(0xffffffffu, sq0, 1); sq0 += __shfl_xor_sync(0xffffffffu, sq0, 2);
    s1  += __shfl_xor_sync(0xffffffffu, s1, 1);  s1  += __shfl_xor_sync(0xffffffffu, s1, 2);
    sq1 += __shfl_xor_sync(0xffffffffu, sq1, 1); sq1 += __shfl_xor_sync(0xffffffffu, sq1, 2);
    float mean0 = s0 * (1.f/128.f);
    float mean1 = s1 * (1.f/128.f);
    float rstd0 = rsqrtf(sq0 * (1.f/128.f) - mean0*mean0 + 1e-5f);
    float rstd1 = rsqrtf(sq1 * (1.f/128.f) - mean1*mean1 + 1e-5f);
#pragma unroll
    for (int nf = 0; nf < 16; nf++) {
        const int cc = nf * 8 + tq * 2;
        float y0 = (acc2[nf][0] - mean0) * rstd0 * lng_s[cc]   + lnb_s[cc];
        float y1 = (acc2[nf][1] - mean0) * rstd0 * lng_s[cc+1] + lnb_s[cc+1];
        float y2 = (acc2[nf][2] - mean1) * rstd1 * lng_s[cc]   + lnb_s[cc];
        float y3 = (acc2[nf][3] - mean1) * rstd1 * lng_s[cc+1] + lnb_s[cc+1];
        *reinterpret_cast<float2*>(outF + (size_t)m0 * 128 + cc) = make_float2(y0, y1);
        *reinterpret_cast<float2*>(outF + (size_t)m1 * 128 + cc) = make_float2(y2, y3);
        *reinterpret_cast<uint32_t*>(outB + (size_t)m0 * 128 + cc) = packbf2(y0, y1);
        *reinterpret_cast<uint32_t*>(outB + (size_t)m1 * 128 + cc) = packbf2(y2, y3);
    }
}

// ======================= Head: FC -> softmax -> rebalance =======================
__global__ __launch_bounds__(512)
void head_kernel(const float* __restrict__ hbuf, const float* __restrict__ fcw,
                 const float* __restrict__ fcb, float* __restrict__ out)
{
    __shared__ float logits[B_][OUT_];
    const int t = threadIdx.x;
    if (t < B_ * OUT_) {
        int b = t / OUT_;
        int o = t % OUT_;
        const float* hr = hbuf + ((size_t)(b * S_ + (S_ - 1))) * D_;
        float acc = fcb[o];
        for (int d = 0; d < D_; d++) acc += hr[d] * fcw[o * D_ + d];
        logits[b][o] = acc;
    }
    __syncthreads();
    if (t < B_) {
        const float UB = 0.3f, LB = 0.0f;
        float wv[OUT_], old[OUT_], wc[OUT_], res[OUT_];
        float mx = -1e30f;
        for (int o = 0; o < OUT_; o++) mx = fmaxf(mx, logits[t][o]);
        float sum = 0.f;
        for (int o = 0; o < OUT_; o++) { wv[o] = expf(logits[t][o] - mx); sum += wv[o]; }
        float inv = 1.f / sum;
        for (int o = 0; o < OUT_; o++) wv[o] *= inv;
        bool done = false;
        for (int o = 0; o < OUT_; o++) {
            old[o] = wv[o];
            wc[o]  = fminf(fmaxf(wv[o], LB), UB);
            res[o] = wv[o];
        }
        for (int it = 0; it < 16; it++) {
            float leftover = 0.f;
            for (int o = 0; o < OUT_; o++) leftover += old[o] - wc[o];
            float denom = 0.f;
            float noms[OUT_];
            for (int o = 0; o < OUT_; o++) {
                noms[o] = (wc[o] != UB) ? wc[o] : 0.f;
                denom += noms[o];
            }
            if (denom == 0.f) denom = 1.f;
            float cand[OUT_];
            bool any = false;
            for (int o = 0; o < OUT_; o++) {
                cand[o] = wc[o] + leftover * noms[o] / denom;
                if (cand[o] > UB) any = true;
            }
            if (!done)
                for (int o = 0; o < OUT_; o++) res[o] = cand[o];
            done = done || !any;
            if (!done) {
                for (int o = 0; o < OUT_; o++) {
                    old[o] = cand[o];
                    wc[o]  = fminf(fmaxf(cand[o], LB), UB);
                }
            }
        }
        for (int o = 0; o < OUT_; o++) out[t * OUT_ + o] = res[o];
    }
}

// ======================= launch =======================
extern "C" void kernel_launch(void* const* d_in, const int* in_sizes, int n_in,
                              void* d_out, int out_size)
{
    const float* x   = (const float*)d_in[0];
    const float* ipw = (const float*)d_in[1];
    const float* ipb = (const float*)d_in[2];
    const float* ow  = (const float*)d_in[3];
    const float* ob  = (const float*)d_in[4];
    const float* l1g = (const float*)d_in[5];
    const float* l1b = (const float*)d_in[6];
    const float* f1w = (const float*)d_in[7];
    const float* f1b = (const float*)d_in[8];
    const float* f2w = (const float*)d_in[9];
    const float* f2b = (const float*)d_in[10];
    const float* l2g = (const float*)d_in[11];
    const float* l2b = (const float*)d_in[12];
    const float* fcw = (const float*)d_in[13];
    const float* fcb = (const float*)d_in[14];

    __nv_bfloat16 *qb, *kb, *vb, *hb, *wip, *wout, *wf1, *wf2;
    float *h;
    cudaGetSymbolAddress((void**)&qb,    g_qb);
    cudaGetSymbolAddress((void**)&kb,    g_kb);
    cudaGetSymbolAddress((void**)&vb,    g_vb);
    cudaGetSymbolAddress((void**)&hb,    g_hb);
    cudaGetSymbolAddress((void**)&h,     g_h);
    cudaGetSymbolAddress((void**)&wip,   g_wip);
    cudaGetSymbolAddress((void**)&wout,  g_wout);
    cudaGetSymbolAddress((void**)&wf1,   g_wf1);
    cudaGetSymbolAddress((void**)&wf2,   g_wf2);

    cudaFuncSetAttribute(attn_fused_kernel, cudaFuncAttributeMaxDynamicSharedMemorySize, AT_SMEM);
    cudaFuncSetAttribute(ffn_kernel,        cudaFuncAttributeMaxDynamicSharedMemorySize, FF_SMEM);

    cvt_kernel<<<(L_*3*D_*D_)/1024, 256>>>(ipw, wip, L_*3*D_*D_);
    cvt_kernel<<<(L_*D_*D_)/1024,   256>>>(ow,  wout, L_*D_*D_);
    cvt_kernel<<<(L_*FF_*D_)/1024,  256>>>(f1w, wf1, L_*FF_*D_);
    cvt_kernel<<<(L_*D_*FF_)/1024,  256>>>(f2w, wf2, L_*D_*FF_);
    cvt_kernel<<<(M_*D_)/1024,      256>>>(x,   hb,  M_*D_);

    for (int l = 0; l < L_; l++) {
        const float* hinF = (l == 0) ? x : h;

        // QKV projection -> q/k/v bf16 [b,h,s,32] (q pre-scaled)
        qkv_kernel<<<dim3(3, M_/128), 256>>>(
            hb, wip + (size_t)l*3*D_*D_, ipb + (size_t)l*3*D_, qb, kb, vb);

        // attention + out-proj + residual + LN1 -> h, hb
        attn_fused_kernel<<<dim3(S_/64, B_), 128, AT_SMEM>>>(
            qb, kb, vb, wout + (size_t)l*D_*D_, ob + (size_t)l*D_,
            hinF, l1g + (size_t)l*D_, l1b + (size_t)l*D_, h, hb);

        // FFN (FF1+relu+FF2) + residual + LN2 -> h, hb
        ffn_kernel<<<M_/64, 128, FF_SMEM>>>(
            hb, wf1 + (size_t)l*FF_*D_, f1b + (size_t)l*FF_,
            wf2 + (size_t)l*D_*FF_, f2b + (size_t)l*D_,
            h, l2g + (size_t)l*D_, l2b + (size_t)l*D_, h, hb);
    }

    head_kernel<<<1, 512>>>(h, fcw, fcb, (float*)d_out);
}

// round 6
// speedup vs baseline: 1.0110x; 1.0110x over previous
#include <cuda_runtime.h>
#include <cuda_bf16.h>
#include <cstdint>
#include <math.h>

#define B_   16
#define S_   2048
#define D_   128
#define H_   4
#define DH_  32
#define FF_  512
#define L_   4
#define OUT_ 30
#define M_   (B_*S_)   // 32768

// log2(e) / sqrt(32): folded into Q so softmax is a bare ex2
#define QSCALE 0.25506626866f

// ======================= low-level helpers =======================
__device__ __forceinline__ void mma16816(float* d, const uint32_t* a, const uint32_t* b) {
    asm volatile("mma.sync.aligned.m16n8k16.row.col.f32.bf16.bf16.f32 "
        "{%0,%1,%2,%3}, {%4,%5,%6,%7}, {%8,%9}, {%0,%1,%2,%3};"
        : "+f"(d[0]), "+f"(d[1]), "+f"(d[2]), "+f"(d[3])
        : "r"(a[0]), "r"(a[1]), "r"(a[2]), "r"(a[3]), "r"(b[0]), "r"(b[1]));
}
__device__ __forceinline__ uint32_t packbf2(float x, float y) {
    __nv_bfloat162 p = __floats2bfloat162_rn(x, y);
    return *(uint32_t*)&p;
}
__device__ __forceinline__ float ex2f(float x) {
    float y; asm("ex2.approx.f32 %0, %1;" : "=f"(y) : "f"(x)); return y;
}
__device__ __forceinline__ uint32_t cvta_s(const void* p) {
    return (uint32_t)__cvta_generic_to_shared(p);
}
__device__ __forceinline__ void cp16(uint32_t dst, const void* src) {
    asm volatile("cp.async.cg.shared.global [%0], [%1], 16;" :: "r"(dst), "l"(src));
}
#define CP_COMMIT() asm volatile("cp.async.commit_group;" ::: "memory")
#define CP_WAIT(n)  asm volatile("cp.async.wait_group %0;" :: "n"(n) : "memory")
__device__ __forceinline__ void ldm_x4(uint32_t* r, uint32_t a) {
    asm volatile("ldmatrix.sync.aligned.m8n8.x4.shared.b16 {%0,%1,%2,%3}, [%4];"
        : "=r"(r[0]), "=r"(r[1]), "=r"(r[2]), "=r"(r[3]) : "r"(a));
}
__device__ __forceinline__ void ldm_x4t(uint32_t* r, uint32_t a) {
    asm volatile("ldmatrix.sync.aligned.m8n8.x4.trans.shared.b16 {%0,%1,%2,%3}, [%4];"
        : "=r"(r[0]), "=r"(r[1]), "=r"(r[2]), "=r"(r[3]) : "r"(a));
}

#define TST  40    // smem stride for 32-wide (k=32) bf16 tiles
#define TSTW 136   // smem stride for 128-wide bf16 tiles

// ======================= scratch (device globals) =======================
__device__ __nv_bfloat16 g_qb[B_*H_*S_*DH_];
__device__ __nv_bfloat16 g_kb[B_*H_*S_*DH_];
__device__ __nv_bfloat16 g_vb[B_*H_*S_*DH_];
__device__ __nv_bfloat16 g_hb[M_*D_];
__device__ float         g_h[M_*D_];
__device__ __nv_bfloat16 g_wip[L_*3*D_*D_];
__device__ __nv_bfloat16 g_wout[L_*D_*D_];
__device__ __nv_bfloat16 g_wf1[L_*FF_*D_];
__device__ __nv_bfloat16 g_wf2[L_*D_*FF_];

// ======================= fp32 -> bf16 conversion =======================
__global__ __launch_bounds__(256) void cvt_kernel(const float* __restrict__ s,
                                                  __nv_bfloat16* __restrict__ d, int n) {
    int i = (blockIdx.x * 256 + threadIdx.x) * 4;
    if (i < n) {
        float4 v = *reinterpret_cast<const float4*>(s + i);
        *reinterpret_cast<uint2*>(d + i) = make_uint2(packbf2(v.x, v.y), packbf2(v.z, v.w));
    }
}

// ======================= QKV projection (bf16 MMA, pipelined) =======================
__global__ __launch_bounds__(256)
void qkv_kernel(const __nv_bfloat16* __restrict__ A, const __nv_bfloat16* __restrict__ W,
                const float* __restrict__ bias,
                __nv_bfloat16* __restrict__ qo, __nv_bfloat16* __restrict__ ko,
                __nv_bfloat16* __restrict__ vo)
{
    __shared__ __nv_bfloat16 As[2][128*TST];
    __shared__ __nv_bfloat16 Bs[2][128*TST];
    __shared__ float bias_s[128];

    const int t    = threadIdx.x;
    const int wid  = t >> 5;
    const int lane = t & 31;
    const int g    = lane >> 2;
    const int tq   = lane & 3;
    const int wm   = wid >> 2;
    const int wn   = wid & 3;
    const int row0 = blockIdx.y * 128;
    const int n0   = blockIdx.x * 128;
    const int K    = D_;

    if (t < 128) bias_s[t] = bias[n0 + t];

    const uint32_t sA[2] = { cvta_s(As[0]), cvta_s(As[1]) };
    const uint32_t sB[2] = { cvta_s(Bs[0]), cvta_s(Bs[1]) };

    auto load_tile = [&](int kt, int stg) {
        const int k0 = kt << 5;
#pragma unroll
        for (int i = 0; i < 2; i++) {
            int id = t + (i << 8);
            int r = id >> 2, qq = id & 3;
            cp16(sA[stg] + r * (TST*2) + qq * 16, &A[(size_t)(row0 + r) * K + k0 + qq * 8]);
            cp16(sB[stg] + r * (TST*2) + qq * 16, &W[(size_t)(n0   + r) * K + k0 + qq * 8]);
        }
    };

    float acc[4][4][4];
#pragma unroll
    for (int mf = 0; mf < 4; mf++)
#pragma unroll
        for (int nf = 0; nf < 4; nf++)
#pragma unroll
            for (int e = 0; e < 4; e++) acc[mf][nf][e] = 0.f;

    load_tile(0, 0);
    CP_COMMIT();

    const int aRow = wm * 64 + (lane & 15);
    const int aColX = (lane >> 4) * 8;
    const int bRow = wn * 32 + (lane & 7) + ((lane >> 4) << 3);
    const int bColX = ((lane >> 3) & 1) * 8;

    for (int kt = 0; kt < 4; kt++) {
        const int stg = kt & 1;
        if (kt + 1 < 4) { load_tile(kt + 1, stg ^ 1); CP_COMMIT(); CP_WAIT(1); }
        else CP_WAIT(0);
        __syncthreads();

#pragma unroll
        for (int ks = 0; ks < 2; ks++) {
            const int kk = ks << 4;
            uint32_t af[4][4];
#pragma unroll
            for (int mf = 0; mf < 4; mf++)
                ldm_x4(af[mf], sA[stg] + ((aRow + mf * 16) * TST + kk + aColX) * 2);
            uint32_t bf[4][2];
#pragma unroll
            for (int pp = 0; pp < 2; pp++) {
                uint32_t r4[4];
                ldm_x4(r4, sB[stg] + ((bRow + pp * 16) * TST + kk + bColX) * 2);
                bf[pp*2][0] = r4[0]; bf[pp*2][1] = r4[1];
                bf[pp*2+1][0] = r4[2]; bf[pp*2+1][1] = r4[3];
            }
#pragma unroll
            for (int mf = 0; mf < 4; mf++)
#pragma unroll
                for (int nf = 0; nf < 4; nf++)
                    mma16816(acc[mf][nf], af[mf], bf[nf]);
        }
        __syncthreads();
    }

#pragma unroll
    for (int mf = 0; mf < 4; mf++) {
        const int m0 = row0 + wm * 64 + mf * 16 + g;
        const int m1 = m0 + 8;
#pragma unroll
        for (int nf = 0; nf < 4; nf++) {
            const int c = wn * 32 + nf * 8 + tq * 2;
            float v0 = acc[mf][nf][0] + bias_s[c];
            float v1 = acc[mf][nf][1] + bias_s[c + 1];
            float v2 = acc[mf][nf][2] + bias_s[c];
            float v3 = acc[mf][nf][3] + bias_s[c + 1];
            __nv_bfloat16* dst = (blockIdx.x == 0) ? qo : ((blockIdx.x == 1) ? ko : vo);
            if (blockIdx.x == 0) { v0 *= QSCALE; v1 *= QSCALE; v2 *= QSCALE; v3 *= QSCALE; }
            const int hh = c >> 5, dd = c & 31;
            int b0i = m0 >> 11, s0i = m0 & 2047;
            int b1i = m1 >> 11, s1i = m1 & 2047;
            *reinterpret_cast<uint32_t*>(dst + ((size_t)(b0i * H_ + hh) * S_ + s0i) * DH_ + dd) = packbf2(v0, v1);
            *reinterpret_cast<uint32_t*>(dst + ((size_t)(b1i * H_ + hh) * S_ + s1i) * DH_ + dd) = packbf2(v2, v3);
        }
    }
}

// ======================= fused attention + out-proj + residual + LN1 =======================
// CTA: (b, 128-query block), 256 threads (8 warps x 16 queries). Heads serial;
// normalized O C-frags feed out-proj A-frags directly; then residual + LN1.
// smem: Qs@0 (10240) Ks@10240 (2x5120) Vs@20480 (2x5120) Wo@30720 (34816) params@65536
#define AT_SMEM (65536 + 1536)
__global__ __launch_bounds__(256)
void attn_fused_kernel(const __nv_bfloat16* __restrict__ q, const __nv_bfloat16* __restrict__ k,
                       const __nv_bfloat16* __restrict__ v, const __nv_bfloat16* __restrict__ Wo,
                       const float* __restrict__ ob, const float* __restrict__ R,
                       const float* __restrict__ lng, const float* __restrict__ lnb,
                       float* __restrict__ outF, __nv_bfloat16* __restrict__ outB)
{
    extern __shared__ char sm[];
    __nv_bfloat16* Qs  = (__nv_bfloat16*)(sm);
    __nv_bfloat16* Ks0 = (__nv_bfloat16*)(sm + 10240);
    __nv_bfloat16* Vs0 = (__nv_bfloat16*)(sm + 20480);
    __nv_bfloat16* Wos = (__nv_bfloat16*)(sm + 30720);
    float* bias_s = (float*)(sm + 65536);
    float* lng_s  = (float*)(sm + 66048);
    float* lnb_s  = (float*)(sm + 66560);

    const int t    = threadIdx.x;
    const int wid  = t >> 5;
    const int lane = t & 31;
    const int g    = lane >> 2;
    const int tq   = lane & 3;
    const int b    = blockIdx.y;
    const int q0   = blockIdx.x * 128;

    const uint32_t sQ = cvta_s(Qs);
    const uint32_t sK[2] = { cvta_s(Ks0), cvta_s(Ks0) + 5120 };
    const uint32_t sV[2] = { cvta_s(Vs0), cvta_s(Vs0) + 5120 };
    const uint32_t sWo = cvta_s(Wos);

    // stage Wo [128 n][128 k] + params
#pragma unroll
    for (int i = 0; i < 8; i++) {
        int id = t + (i << 8);
        int r = id >> 4, cc = id & 15;
        cp16(sWo + (r * TSTW + cc * 8) * 2, &Wo[(size_t)r * 128 + cc * 8]);
    }
    if (t < 128) { bias_s[t] = ob[t]; lng_s[t] = lng[t]; lnb_s[t] = lnb[t]; }
    CP_COMMIT();

    // ldmatrix lane-offsets
    const int aRow = wid * 16 + (lane & 15);
    const int aColX = (lane >> 4) * 8;
    const int bRow = (lane & 7) + ((lane >> 4) << 3);
    const int bColX = ((lane >> 3) & 1) * 8;
    const int vRow = (lane & 7) + (((lane >> 3) & 1) << 3);
    const int vColX = (lane >> 4) * 8;

    uint32_t oa[8][4];   // out-proj A k-frags: [h*2+kf][4]

    for (int h = 0; h < H_; h++) {
        const int bh = b * H_ + h;
        // load Q_h (128x32) + KV tile 0 into stage 0
#pragma unroll
        for (int i = 0; i < 2; i++) {
            int id = t + (i << 8);
            int r = id >> 2, qq = id & 3;
            cp16(sQ + r * (TST*2) + qq * 16, &q[((size_t)bh * S_ + q0 + r) * DH_ + qq * 8]);
        }
        {
            int r = t >> 2, qq = t & 3;
            cp16(sK[0] + r * (TST*2) + qq * 16, &k[((size_t)bh * S_ + r) * DH_ + qq * 8]);
            cp16(sV[0] + r * (TST*2) + qq * 16, &v[((size_t)bh * S_ + r) * DH_ + qq * 8]);
        }
        CP_COMMIT();

        float o4[4][4];
        float lg = 0.f, lg8 = 0.f;
#pragma unroll
        for (int nf = 0; nf < 4; nf++)
#pragma unroll
            for (int e = 0; e < 4; e++) o4[nf][e] = 0.f;
        uint32_t af2[2][4];

        for (int it = 0; it < (S_ >> 6); it++) {
            const int stg = it & 1;
            if (it + 1 < (S_ >> 6)) {
                const int j0 = (it + 1) << 6;
                int r = t >> 2, qq = t & 3;
                cp16(sK[stg^1] + r * (TST*2) + qq * 16, &k[((size_t)bh * S_ + j0 + r) * DH_ + qq * 8]);
                cp16(sV[stg^1] + r * (TST*2) + qq * 16, &v[((size_t)bh * S_ + j0 + r) * DH_ + qq * 8]);
                CP_COMMIT(); CP_WAIT(1);
            } else CP_WAIT(0);
            __syncthreads();

            if (it == 0) {
#pragma unroll
                for (int ks = 0; ks < 2; ks++)
                    ldm_x4(af2[ks], sQ + (aRow * TST + ks * 16 + aColX) * 2);
            }

            // S = Q @ K^T
            float sc[8][4];
#pragma unroll
            for (int nf = 0; nf < 8; nf++)
#pragma unroll
                for (int e = 0; e < 4; e++) sc[nf][e] = 0.f;
#pragma unroll
            for (int ks = 0; ks < 2; ks++) {
                const int kk = ks << 4;
#pragma unroll
                for (int pp = 0; pp < 4; pp++) {
                    uint32_t r4[4];
                    ldm_x4(r4, sK[stg] + ((pp * 16 + bRow) * TST + kk + bColX) * 2);
                    uint32_t b0[2] = { r4[0], r4[1] }, b1[2] = { r4[2], r4[3] };
                    mma16816(sc[pp*2],   af2[ks], b0);
                    mma16816(sc[pp*2+1], af2[ks], b1);
                }
            }

            // p = ex2(s); accumulate l; pack P A-frags
            uint32_t pb[8][2];
#pragma unroll
            for (int nf = 0; nf < 8; nf++) {
                float p0 = ex2f(sc[nf][0]);
                float p1 = ex2f(sc[nf][1]);
                float p2 = ex2f(sc[nf][2]);
                float p3 = ex2f(sc[nf][3]);
                lg  += p0 + p1;
                lg8 += p2 + p3;
                pb[nf][0] = packbf2(p0, p1);
                pb[nf][1] = packbf2(p2, p3);
            }

            // O += P @ V
#pragma unroll
            for (int kf = 0; kf < 4; kf++) {
                uint32_t a4[4] = { pb[2*kf][0], pb[2*kf][1], pb[2*kf+1][0], pb[2*kf+1][1] };
#pragma unroll
                for (int pp = 0; pp < 2; pp++) {
                    uint32_t r4[4];
                    ldm_x4t(r4, sV[stg] + ((kf * 16 + vRow) * TST + pp * 16 + vColX) * 2);
                    uint32_t b0[2] = { r4[0], r4[1] }, b1[2] = { r4[2], r4[3] };
                    mma16816(o4[pp*2],   a4, b0);
                    mma16816(o4[pp*2+1], a4, b1);
                }
            }
            __syncthreads();
        }

        // normalize + pack O C-frags as out-proj A k-frags
        lg  += __shfl_xor_sync(0xffffffffu, lg, 1);
        lg  += __shfl_xor_sync(0xffffffffu, lg, 2);
        lg8 += __shfl_xor_sync(0xffffffffu, lg8, 1);
        lg8 += __shfl_xor_sync(0xffffffffu, lg8, 2);
        const float inv0 = 1.f / lg;
        const float inv1 = 1.f / lg8;
#pragma unroll
        for (int kf = 0; kf < 2; kf++) {
            oa[h*2+kf][0] = packbf2(o4[2*kf][0]   * inv0, o4[2*kf][1]   * inv0);
            oa[h*2+kf][1] = packbf2(o4[2*kf][2]   * inv1, o4[2*kf][3]   * inv1);
            oa[h*2+kf][2] = packbf2(o4[2*kf+1][0] * inv0, o4[2*kf+1][1] * inv0);
            oa[h*2+kf][3] = packbf2(o4[2*kf+1][2] * inv1, o4[2*kf+1][3] * inv1);
        }
    }

    // ---- out-projection: [128,128] @ Wo^T, from registers ----
    float acc2[16][4];
#pragma unroll
    for (int nf = 0; nf < 16; nf++)
#pragma unroll
        for (int e = 0; e < 4; e++) acc2[nf][e] = 0.f;
#pragma unroll
    for (int kf = 0; kf < 8; kf++) {
#pragma unroll
        for (int np = 0; np < 8; np++) {
            uint32_t r4[4];
            ldm_x4(r4, sWo + ((np * 16 + bRow) * TSTW + kf * 16 + bColX) * 2);
            uint32_t b0[2] = { r4[0], r4[1] }, b1[2] = { r4[2], r4[3] };
            mma16816(acc2[np*2],   oa[kf], b0);
            mma16816(acc2[np*2+1], oa[kf], b1);
        }
    }

    // ---- bias + residual + LayerNorm ----
    const int m0 = b * S_ + q0 + wid * 16 + g;
    const int m1 = m0 + 8;
    float s0 = 0.f, sq0 = 0.f, s1 = 0.f, sq1 = 0.f;
#pragma unroll
    for (int nf = 0; nf < 16; nf++) {
        const int c = nf * 8 + tq * 2;
        float2 r0 = *reinterpret_cast<const float2*>(R + (size_t)m0 * 128 + c);
        float2 r1 = *reinterpret_cast<const float2*>(R + (size_t)m1 * 128 + c);
        float v0 = acc2[nf][0] + bias_s[c]     + r0.x;
        float v1 = acc2[nf][1] + bias_s[c + 1] + r0.y;
        float v2 = acc2[nf][2] + bias_s[c]     + r1.x;
        float v3 = acc2[nf][3] + bias_s[c + 1] + r1.y;
        acc2[nf][0] = v0; acc2[nf][1] = v1; acc2[nf][2] = v2; acc2[nf][3] = v3;
        s0 += v0 + v1; sq0 += v0*v0 + v1*v1;
        s1 += v2 + v3; sq1 += v2*v2 + v3*v3;
    }
    s0  += __shfl_xor_sync(0xffffffffu, s0, 1);  s0  += __shfl_xor_sync(0xffffffffu, s0, 2);
    sq0 += __shfl_xor_sync(0xffffffffu, sq0, 1); sq0 += __shfl_xor_sync(0xffffffffu, sq0, 2);
    s1  += __shfl_xor_sync(0xffffffffu, s1, 1);  s1  += __shfl_xor_sync(0xffffffffu, s1, 2);
    sq1 += __shfl_xor_sync(0xffffffffu, sq1, 1); sq1 += __shfl_xor_sync(0xffffffffu, sq1, 2);
    float mean0 = s0 * (1.f/128.f);
    float mean1 = s1 * (1.f/128.f);
    float rstd0 = rsqrtf(sq0 * (1.f/128.f) - mean0*mean0 + 1e-5f);
    float rstd1 = rsqrtf(sq1 * (1.f/128.f) - mean1*mean1 + 1e-5f);
#pragma unroll
    for (int nf = 0; nf < 16; nf++) {
        const int c = nf * 8 + tq * 2;
        float y0 = (acc2[nf][0] - mean0) * rstd0 * lng_s[c]   + lnb_s[c];
        float y1 = (acc2[nf][1] - mean0) * rstd0 * lng_s[c+1] + lnb_s[c+1];
        float y2 = (acc2[nf][2] - mean1) * rstd1 * lng_s[c]   + lnb_s[c];
        float y3 = (acc2[nf][3] - mean1) * rstd1 * lng_s[c+1] + lnb_s[c+1];
        *reinterpret_cast<float2*>(outF + (size_t)m0 * 128 + c) = make_float2(y0, y1);
        *reinterpret_cast<float2*>(outF + (size_t)m1 * 128 + c) = make_float2(y2, y3);
        *reinterpret_cast<uint32_t*>(outB + (size_t)m0 * 128 + c) = packbf2(y0, y1);
        *reinterpret_cast<uint32_t*>(outB + (size_t)m1 * 128 + c) = packbf2(y2, y3);
    }
}

// ======================= fused FFN + residual + LN2 =======================
// CTA = 128 rows, 256 threads (8 warps x 16 rows). FF in 4 chunks of 128.
// smem: As@0 (34816) W1s@34816 W2s@69632 b1s@104448 b2s@106496 ln@107008
#define FF_SMEM 108032
__global__ __launch_bounds__(256)
void ffn_kernel(const __nv_bfloat16* __restrict__ Ain,
                const __nv_bfloat16* __restrict__ W1, const float* __restrict__ b1,
                const __nv_bfloat16* __restrict__ W2, const float* __restrict__ b2,
                const float* __restrict__ R, const float* __restrict__ lng,
                const float* __restrict__ lnb,
                float* __restrict__ outF, __nv_bfloat16* __restrict__ outB)
{
    extern __shared__ char sm[];
    __nv_bfloat16* As  = (__nv_bfloat16*)(sm);
    __nv_bfloat16* W1s = (__nv_bfloat16*)(sm + 34816);
    __nv_bfloat16* W2s = (__nv_bfloat16*)(sm + 69632);
    float* b1s  = (float*)(sm + 104448);
    float* b2s  = (float*)(sm + 106496);
    float* lng_s = (float*)(sm + 107008);
    float* lnb_s = (float*)(sm + 107520);

    const int t    = threadIdx.x;
    const int wid  = t >> 5;
    const int lane = t & 31;
    const int g    = lane >> 2;
    const int tq   = lane & 3;
    const int row0 = blockIdx.x * 128;

    const uint32_t sA  = cvta_s(As);
    const uint32_t sW1 = cvta_s(W1s);
    const uint32_t sW2 = cvta_s(W2s);

    auto loadW = [&](int c) {
#pragma unroll
        for (int i = 0; i < 8; i++) {
            int id = t + (i << 8);
            int r = id >> 4, cc = id & 15;
            cp16(sW1 + (r * TSTW + cc * 8) * 2, &W1[(size_t)(c * 128 + r) * 128 + cc * 8]);
            cp16(sW2 + (r * TSTW + cc * 8) * 2, &W2[(size_t)r * 512 + c * 128 + cc * 8]);
        }
    };

    // A tile (128 x 128) + first W chunk + params
#pragma unroll
    for (int i = 0; i < 8; i++) {
        int id = t + (i << 8);
        int r = id >> 4, cc = id & 15;
        cp16(sA + (r * TSTW + cc * 8) * 2, &Ain[(size_t)(row0 + r) * 128 + cc * 8]);
    }
    loadW(0);
#pragma unroll
    for (int i = 0; i < 2; i++) b1s[t + (i << 8)] = b1[t + (i << 8)];
    if (t < 128) { b2s[t] = b2[t]; lng_s[t] = lng[t]; lnb_s[t] = lnb[t]; }
    CP_COMMIT();
    CP_WAIT(0);
    __syncthreads();

    const int aRow = wid * 16 + (lane & 15);
    const int aColX = (lane >> 4) * 8;
    const int bRow = (lane & 7) + ((lane >> 4) << 3);
    const int bColX = ((lane >> 3) & 1) * 8;

    // hoist A fragments (k=128 -> 8 k-frags)
    uint32_t afA[8][4];
#pragma unroll
    for (int kf = 0; kf < 8; kf++)
        ldm_x4(afA[kf], sA + (aRow * TSTW + kf * 16 + aColX) * 2);

    float acc2[16][4];
#pragma unroll
    for (int nf = 0; nf < 16; nf++)
#pragma unroll
        for (int e = 0; e < 4; e++) acc2[nf][e] = 0.f;

    for (int c = 0; c < 4; c++) {
        // GEMM1: T = A @ W1chunk^T
        float acc1[16][4];
#pragma unroll
        for (int nf = 0; nf < 16; nf++)
#pragma unroll
            for (int e = 0; e < 4; e++) acc1[nf][e] = 0.f;
#pragma unroll
        for (int kf = 0; kf < 8; kf++) {
#pragma unroll
            for (int np = 0; np < 8; np++) {
                uint32_t r4[4];
                ldm_x4(r4, sW1 + ((np * 16 + bRow) * TSTW + kf * 16 + bColX) * 2);
                uint32_t b0[2] = { r4[0], r4[1] }, b1f[2] = { r4[2], r4[3] };
                mma16816(acc1[np*2],   afA[kf], b0);
                mma16816(acc1[np*2+1], afA[kf], b1f);
            }
        }
        // relu + bias -> GEMM2 A k-frags
        uint32_t a1[8][4];
#pragma unroll
        for (int nf = 0; nf < 16; nf++) {
            const int col = c * 128 + nf * 8 + tq * 2;
            float v0 = fmaxf(acc1[nf][0] + b1s[col],     0.f);
            float v1 = fmaxf(acc1[nf][1] + b1s[col + 1], 0.f);
            float v2 = fmaxf(acc1[nf][2] + b1s[col],     0.f);
            float v3 = fmaxf(acc1[nf][3] + b1s[col + 1], 0.f);
            const int kf2 = nf >> 1;
            if ((nf & 1) == 0) { a1[kf2][0] = packbf2(v0, v1); a1[kf2][1] = packbf2(v2, v3); }
            else               { a1[kf2][2] = packbf2(v0, v1); a1[kf2][3] = packbf2(v2, v3); }
        }
        // GEMM2: acc2 += T @ W2chunk^T
#pragma unroll
        for (int kf = 0; kf < 8; kf++) {
#pragma unroll
            for (int np = 0; np < 8; np++) {
                uint32_t r4[4];
                ldm_x4(r4, sW2 + ((np * 16 + bRow) * TSTW + kf * 16 + bColX) * 2);
                uint32_t b0[2] = { r4[0], r4[1] }, b1f[2] = { r4[2], r4[3] };
                mma16816(acc2[np*2],   a1[kf], b0);
                mma16816(acc2[np*2+1], a1[kf], b1f);
            }
        }
        __syncthreads();
        if (c < 3) {
            loadW(c + 1);
            CP_COMMIT(); CP_WAIT(0);
            __syncthreads();
        }
    }

    // ---- bias + residual + LayerNorm ----
    const int m0 = row0 + wid * 16 + g;
    const int m1 = m0 + 8;
    float s0 = 0.f, sq0 = 0.f, s1 = 0.f, sq1 = 0.f;
#pragma unroll
    for (int nf = 0; nf < 16; nf++) {
        const int cc = nf * 8 + tq * 2;
        float2 r0 = *reinterpret_cast<const float2*>(R + (size_t)m0 * 128 + cc);
        float2 r1 = *reinterpret_cast<const float2*>(R + (size_t)m1 * 128 + cc);
        float v0 = acc2[nf][0] + b2s[cc]     + r0.x;
        float v1 = acc2[nf][1] + b2s[cc + 1] + r0.y;
        float v2 = acc2[nf][2] + b2s[cc]     + r1.x;
        float v3 = acc2[nf][3] + b2s[cc + 1] + r1.y;
        acc2[nf][0] = v0; acc2[nf][1] = v1; acc2[nf][2] = v2; acc2[nf][3] = v3;
        s0 += v0 + v1; sq0 += v0*v0 + v1*v1;
        s1 += v2 + v3; sq1 += v2*v2 + v3*v3;
    }
    s0  += __shfl_xor_sync(0xffffffffu, s0, 1);  s0  += __shfl_xor_sync(0xffffffffu, s0, 2);
    sq0 += __shfl_xor_sync(0xffffffffu, sq0, 1); sq0 += __shfl_xor_sync(0xffffffffu, sq0, 2);
    s1  += __shfl_xor_sync(0xffffffffu, s1, 1);  s1  += __shfl_xor_sync(0xffffffffu, s1, 2);
    sq1 += __shfl_xor_sync(0xffffffffu, sq1, 1); sq1 += __shfl_xor_sync(0xffffffffu, sq1, 2);
    float mean0 = s0 * (1.f/128.f);
    float mean1 = s1 * (1.f/128.f);
    float rstd0 = rsqrtf(sq0 * (1.f/128.f) - mean0*mean0 + 1e-5f);
    float rstd1 = rsqrtf(sq1 * (1.f/128.f) - mean1*mean1 + 1e-5f);
#pragma unroll
    for (int nf = 0; nf < 16; nf++) {
        const int cc = nf * 8 + tq * 2;
        float y0 = (acc2[nf][0] - mean0) * rstd0 * lng_s[cc]   + lnb_s[cc];
        float y1 = (acc2[nf][1] - mean0) * rstd0 * lng_s[cc+1] + lnb_s[cc+1];
        float y2 = (acc2[nf][2] - mean1) * rstd1 * lng_s[cc]   + lnb_s[cc];
        float y3 = (acc2[nf][3] - mean1) * rstd1 * lng_s[cc+1] + lnb_s[cc+1];
        *reinterpret_cast<float2*>(outF + (size_t)m0 * 128 + cc) = make_float2(y0, y1);
        *reinterpret_cast<float2*>(outF + (size_t)m1 * 128 + cc) = make_float2(y2, y3);
        *reinterpret_cast<uint32_t*>(outB + (size_t)m0 * 128 + cc) = packbf2(y0, y1);
        *reinterpret_cast<uint32_t*>(outB + (size_t)m1 * 128 + cc) = packbf2(y2, y3);
    }
}

// ======================= Head: FC -> softmax -> rebalance =======================
__global__ __launch_bounds__(512)
void head_kernel(const float* __restrict__ hbuf, const float* __restrict__ fcw,
                 const float* __restrict__ fcb, float* __restrict__ out)
{
    __shared__ float logits[B_][OUT_];
    const int t = threadIdx.x;
    if (t < B_ * OUT_) {
        int b = t / OUT_;
        int o = t % OUT_;
        const float* hr = hbuf + ((size_t)(b * S_ + (S_ - 1))) * D_;
        float acc = fcb[o];
        for (int d = 0; d < D_; d++) acc += hr[d] * fcw[o * D_ + d];
        logits[b][o] = acc;
    }
    __syncthreads();
    if (t < B_) {
        const float UB = 0.3f, LB = 0.0f;
        float wv[OUT_], old[OUT_], wc[OUT_], res[OUT_];
        float mx = -1e30f;
        for (int o = 0; o < OUT_; o++) mx = fmaxf(mx, logits[t][o]);
        float sum = 0.f;
        for (int o = 0; o < OUT_; o++) { wv[o] = expf(logits[t][o] - mx); sum += wv[o]; }
        float inv = 1.f / sum;
        for (int o = 0; o < OUT_; o++) wv[o] *= inv;
        bool done = false;
        for (int o = 0; o < OUT_; o++) {
            old[o] = wv[o];
            wc[o]  = fminf(fmaxf(wv[o], LB), UB);
            res[o] = wv[o];
        }
        for (int it = 0; it < 16; it++) {
            float leftover = 0.f;
            for (int o = 0; o < OUT_; o++) leftover += old[o] - wc[o];
            float denom = 0.f;
            float noms[OUT_];
            for (int o = 0; o < OUT_; o++) {
                noms[o] = (wc[o] != UB) ? wc[o] : 0.f;
                denom += noms[o];
            }
            if (denom == 0.f) denom = 1.f;
            float cand[OUT_];
            bool any = false;
            for (int o = 0; o < OUT_; o++) {
                cand[o] = wc[o] + leftover * noms[o] / denom;
                if (cand[o] > UB) any = true;
            }
            if (!done)
                for (int o = 0; o < OUT_; o++) res[o] = cand[o];
            done = done || !any;
            if (!done) {
                for (int o = 0; o < OUT_; o++) {
                    old[o] = cand[o];
                    wc[o]  = fminf(fmaxf(cand[o], LB), UB);
                }
            }
        }
        for (int o = 0; o < OUT_; o++) out[t * OUT_ + o] = res[o];
    }
}

// ======================= launch =======================
extern "C" void kernel_launch(void* const* d_in, const int* in_sizes, int n_in,
                              void* d_out, int out_size)
{
    const float* x   = (const float*)d_in[0];
    const float* ipw = (const float*)d_in[1];
    const float* ipb = (const float*)d_in[2];
    const float* ow  = (const float*)d_in[3];
    const float* ob  = (const float*)d_in[4];
    const float* l1g = (const float*)d_in[5];
    const float* l1b = (const float*)d_in[6];
    const float* f1w = (const float*)d_in[7];
    const float* f1b = (const float*)d_in[8];
    const float* f2w = (const float*)d_in[9];
    const float* f2b = (const float*)d_in[10];
    const float* l2g = (const float*)d_in[11];
    const float* l2b = (const float*)d_in[12];
    const float* fcw = (const float*)d_in[13];
    const float* fcb = (const float*)d_in[14];

    __nv_bfloat16 *qb, *kb, *vb, *hb, *wip, *wout, *wf1, *wf2;
    float *h;
    cudaGetSymbolAddress((void**)&qb,    g_qb);
    cudaGetSymbolAddress((void**)&kb,    g_kb);
    cudaGetSymbolAddress((void**)&vb,    g_vb);
    cudaGetSymbolAddress((void**)&hb,    g_hb);
    cudaGetSymbolAddress((void**)&h,     g_h);
    cudaGetSymbolAddress((void**)&wip,   g_wip);
    cudaGetSymbolAddress((void**)&wout,  g_wout);
    cudaGetSymbolAddress((void**)&wf1,   g_wf1);
    cudaGetSymbolAddress((void**)&wf2,   g_wf2);

    cudaFuncSetAttribute(attn_fused_kernel, cudaFuncAttributeMaxDynamicSharedMemorySize, AT_SMEM);
    cudaFuncSetAttribute(ffn_kernel,        cudaFuncAttributeMaxDynamicSharedMemorySize, FF_SMEM);

    cvt_kernel<<<(L_*3*D_*D_)/1024, 256>>>(ipw, wip, L_*3*D_*D_);
    cvt_kernel<<<(L_*D_*D_)/1024,   256>>>(ow,  wout, L_*D_*D_);
    cvt_kernel<<<(L_*FF_*D_)/1024,  256>>>(f1w, wf1, L_*FF_*D_);
    cvt_kernel<<<(L_*D_*FF_)/1024,  256>>>(f2w, wf2, L_*D_*FF_);
    cvt_kernel<<<(M_*D_)/1024,      256>>>(x,   hb,  M_*D_);

    for (int l = 0; l < L_; l++) {
        const float* hinF = (l == 0) ? x : h;

        // QKV projection -> q/k/v bf16 [b,h,s,32] (q pre-scaled)
        qkv_kernel<<<dim3(3, M_/128), 256>>>(
            hb, wip + (size_t)l*3*D_*D_, ipb + (size_t)l*3*D_, qb, kb, vb);

        // attention + out-proj + residual + LN1 -> h, hb
        attn_fused_kernel<<<dim3(S_/128, B_), 256, AT_SMEM>>>(
            qb, kb, vb, wout + (size_t)l*D_*D_, ob + (size_t)l*D_,
            hinF, l1g + (size_t)l*D_, l1b + (size_t)l*D_, h, hb);

        // FFN (FF1+relu+FF2) + residual + LN2 -> h, hb
        ffn_kernel<<<M_/128, 256, FF_SMEM>>>(
            hb, wf1 + (size_t)l*FF_*D_, f1b + (size_t)l*FF_,
            wf2 + (size_t)l*D_*FF_, f2b + (size_t)l*D_,
            h, l2g + (size_t)l*D_, l2b + (size_t)l*D_, h, hb);
    }

    head_kernel<<<1, 512>>>(h, fcw, fcb, (float*)d_out);
}

// round 7
// speedup vs baseline: 1.2142x; 1.2009x over previous
#include <cuda_runtime.h>
#include <cuda_bf16.h>
#include <cstdint>
#include <math.h>

#define B_   16
#define S_   2048
#define D_   128
#define H_   4
#define DH_  32
#define FF_  512
#define L_   4
#define OUT_ 30
#define M_   (B_*S_)   // 32768

// log2(e) / sqrt(32): folded into Q so softmax is a bare ex2
#define QSCALE 0.25506626866f

// ======================= low-level helpers =======================
__device__ __forceinline__ void mma16816(float* d, const uint32_t* a, const uint32_t* b) {
    asm volatile("mma.sync.aligned.m16n8k16.row.col.f32.bf16.bf16.f32 "
        "{%0,%1,%2,%3}, {%4,%5,%6,%7}, {%8,%9}, {%0,%1,%2,%3};"
        : "+f"(d[0]), "+f"(d[1]), "+f"(d[2]), "+f"(d[3])
        : "r"(a[0]), "r"(a[1]), "r"(a[2]), "r"(a[3]), "r"(b[0]), "r"(b[1]));
}
__device__ __forceinline__ uint32_t packbf2(float x, float y) {
    __nv_bfloat162 p = __floats2bfloat162_rn(x, y);
    return *(uint32_t*)&p;
}
__device__ __forceinline__ float ex2f(float x) {
    float y; asm("ex2.approx.f32 %0, %1;" : "=f"(y) : "f"(x)); return y;
}
__device__ __forceinline__ uint32_t cvta_s(const void* p) {
    return (uint32_t)__cvta_generic_to_shared(p);
}
__device__ __forceinline__ void cp16(uint32_t dst, const void* src) {
    asm volatile("cp.async.cg.shared.global [%0], [%1], 16;" :: "r"(dst), "l"(src));
}
#define CP_COMMIT() asm volatile("cp.async.commit_group;" ::: "memory")
#define CP_WAIT(n)  asm volatile("cp.async.wait_group %0;" :: "n"(n) : "memory")
__device__ __forceinline__ void ldm_x4(uint32_t* r, uint32_t a) {
    asm volatile("ldmatrix.sync.aligned.m8n8.x4.shared.b16 {%0,%1,%2,%3}, [%4];"
        : "=r"(r[0]), "=r"(r[1]), "=r"(r[2]), "=r"(r[3]) : "r"(a));
}
__device__ __forceinline__ void ldm_x4t(uint32_t* r, uint32_t a) {
    asm volatile("ldmatrix.sync.aligned.m8n8.x4.trans.shared.b16 {%0,%1,%2,%3}, [%4];"
        : "=r"(r[0]), "=r"(r[1]), "=r"(r[2]), "=r"(r[3]) : "r"(a));
}

#define TST  40    // smem row stride (elements) for 32-wide tiles

// ======================= scratch (device globals) =======================
__device__ __nv_bfloat16 g_qb[B_*H_*S_*DH_];
__device__ __nv_bfloat16 g_kb[B_*H_*S_*DH_];
__device__ __nv_bfloat16 g_vb[B_*H_*S_*DH_];
__device__ __nv_bfloat16 g_attnb[M_*D_];
__device__ __nv_bfloat16 g_hb[M_*D_];
__device__ float         g_h[M_*D_];
__device__ __nv_bfloat16 g_ffb[(size_t)M_*FF_];
__device__ __nv_bfloat16 g_wip[L_*3*D_*D_];
__device__ __nv_bfloat16 g_wout[L_*D_*D_];
__device__ __nv_bfloat16 g_wf1[L_*FF_*D_];
__device__ __nv_bfloat16 g_wf2[L_*D_*FF_];

// ======================= fp32 -> bf16 conversion =======================
__global__ __launch_bounds__(256) void cvt_kernel(const float* __restrict__ s,
                                                  __nv_bfloat16* __restrict__ d, int n) {
    int i = (blockIdx.x * 256 + threadIdx.x) * 4;
    if (i < n) {
        float4 v = *reinterpret_cast<const float4*>(s + i);
        *reinterpret_cast<uint2*>(d + i) = make_uint2(packbf2(v.x, v.y), packbf2(v.z, v.w));
    }
}

// ======================= pipelined bf16 MMA GEMM (3-stage) =======================
// C[128x128 tile] = A[M,K] @ W[N,K]^T + bias. 8 warps (2M x 4N), warp tile 64x32.
// EPI 0: scatter q/k/v bf16; q pre-scaled (blockIdx.x picks q/k/v)
// EPI 1: relu -> bf16 [M, Nstride]
// EPI 2: +residual(fp32) -> fused LayerNorm -> fp32 h + bf16 hb
// smem (dynamic): As s@s*10240, Bs s@30720+s*10240, bias@61440, lng@61952,
//                 lnb@62464, redS@62976, redQ@65024  (total 67072)
#define MM_SMEM 67072
template<int EPI>
__global__ __launch_bounds__(256)
void mm_kernel(const __nv_bfloat16* __restrict__ A, const __nv_bfloat16* __restrict__ W,
               const float* __restrict__ bias, const float* __restrict__ R,
               const float* __restrict__ lng, const float* __restrict__ lnb,
               float* __restrict__ outF, __nv_bfloat16* __restrict__ outB,
               __nv_bfloat16* __restrict__ qo, __nv_bfloat16* __restrict__ ko,
               __nv_bfloat16* __restrict__ vo, int Nstride, int K)
{
    extern __shared__ char smx[];
    const uint32_t sbase = cvta_s(smx);
    float* bias_s = (float*)(smx + 61440);
    float* lng_s  = (float*)(smx + 61952);
    float* lnb_s  = (float*)(smx + 62464);
    float (*redS)[4] = (float(*)[4])(smx + 62976);
    float (*redQ)[4] = (float(*)[4])(smx + 65024);

    const int t    = threadIdx.x;
    const int wid  = t >> 5;
    const int lane = t & 31;
    const int g    = lane >> 2;
    const int tq   = lane & 3;
    const int wm   = wid >> 2;
    const int wn   = wid & 3;
    const int row0 = blockIdx.y * 128;
    const int n0   = blockIdx.x * 128;

    if (t < 128) {
        bias_s[t] = bias[n0 + t];
        if (EPI == 2) { lng_s[t] = lng[t]; lnb_s[t] = lnb[t]; }
    }

    auto sA = [&](int s) -> uint32_t { return sbase + s * 10240; };
    auto sB = [&](int s) -> uint32_t { return sbase + 30720 + s * 10240; };

    auto load_tile = [&](int kt, int stg) {
        const int k0 = kt << 5;
#pragma unroll
        for (int i = 0; i < 2; i++) {
            int id = t + (i << 8);
            int r = id >> 2, qq = id & 3;
            cp16(sA(stg) + r * (TST*2) + qq * 16, &A[(size_t)(row0 + r) * K + k0 + qq * 8]);
            cp16(sB(stg) + r * (TST*2) + qq * 16, &W[(size_t)(n0   + r) * K + k0 + qq * 8]);
        }
    };

    float acc[4][4][4];
#pragma unroll
    for (int mf = 0; mf < 4; mf++)
#pragma unroll
        for (int nf = 0; nf < 4; nf++)
#pragma unroll
            for (int e = 0; e < 4; e++) acc[mf][nf][e] = 0.f;

    const int nkt = K >> 5;
    load_tile(0, 0); CP_COMMIT();
    if (nkt > 1) { load_tile(1, 1); CP_COMMIT(); }

    const int aRow = wm * 64 + (lane & 15);
    const int aColX = (lane >> 4) * 8;
    const int bRow = wn * 32 + (lane & 7) + ((lane >> 4) << 3);
    const int bColX = ((lane >> 3) & 1) * 8;

    for (int kt = 0; kt < nkt; kt++) {
        const int stg = kt % 3;
        if (kt < nkt - 1) CP_WAIT(1); else CP_WAIT(0);
        __syncthreads();
        if (kt + 2 < nkt) { load_tile(kt + 2, (kt + 2) % 3); CP_COMMIT(); }

#pragma unroll
        for (int ks = 0; ks < 2; ks++) {
            const int kk = ks << 4;
            uint32_t af[4][4];
#pragma unroll
            for (int mf = 0; mf < 4; mf++)
                ldm_x4(af[mf], sA(stg) + ((aRow + mf * 16) * TST + kk + aColX) * 2);
            uint32_t bf[4][2];
#pragma unroll
            for (int pp = 0; pp < 2; pp++) {
                uint32_t r4[4];
                ldm_x4(r4, sB(stg) + ((bRow + pp * 16) * TST + kk + bColX) * 2);
                bf[pp*2][0] = r4[0]; bf[pp*2][1] = r4[1];
                bf[pp*2+1][0] = r4[2]; bf[pp*2+1][1] = r4[3];
            }
#pragma unroll
            for (int mf = 0; mf < 4; mf++)
#pragma unroll
                for (int nf = 0; nf < 4; nf++)
                    mma16816(acc[mf][nf], af[mf], bf[nf]);
        }
    }

    // ---- epilogue ----
    if (EPI == 2) {
#pragma unroll
        for (int mf = 0; mf < 4; mf++) {
            const int m0 = row0 + wm * 64 + mf * 16 + g;
            const int m1 = m0 + 8;
            float s0 = 0.f, q0 = 0.f, s1 = 0.f, q1 = 0.f;
#pragma unroll
            for (int nf = 0; nf < 4; nf++) {
                const int c = wn * 32 + nf * 8 + tq * 2;
                float2 r0 = *reinterpret_cast<const float2*>(R + (size_t)m0 * 128 + c);
                float2 r1 = *reinterpret_cast<const float2*>(R + (size_t)m1 * 128 + c);
                float v0 = acc[mf][nf][0] + bias_s[c]     + r0.x;
                float v1 = acc[mf][nf][1] + bias_s[c + 1] + r0.y;
                float v2 = acc[mf][nf][2] + bias_s[c]     + r1.x;
                float v3 = acc[mf][nf][3] + bias_s[c + 1] + r1.y;
                acc[mf][nf][0] = v0; acc[mf][nf][1] = v1;
                acc[mf][nf][2] = v2; acc[mf][nf][3] = v3;
                s0 += v0 + v1; q0 += v0*v0 + v1*v1;
                s1 += v2 + v3; q1 += v2*v2 + v3*v3;
            }
            s0 += __shfl_xor_sync(0xffffffffu, s0, 1); s0 += __shfl_xor_sync(0xffffffffu, s0, 2);
            q0 += __shfl_xor_sync(0xffffffffu, q0, 1); q0 += __shfl_xor_sync(0xffffffffu, q0, 2);
            s1 += __shfl_xor_sync(0xffffffffu, s1, 1); s1 += __shfl_xor_sync(0xffffffffu, s1, 2);
            q1 += __shfl_xor_sync(0xffffffffu, q1, 1); q1 += __shfl_xor_sync(0xffffffffu, q1, 2);
            if (tq == 0) {
                const int rl = wm * 64 + mf * 16 + g;
                redS[rl][wn] = s0; redQ[rl][wn] = q0;
                redS[rl + 8][wn] = s1; redQ[rl + 8][wn] = q1;
            }
        }
        __syncthreads();
#pragma unroll
        for (int mf = 0; mf < 4; mf++) {
            const int rl = wm * 64 + mf * 16 + g;
            const int m0 = row0 + rl, m1 = m0 + 8;
            float sum0 = redS[rl][0] + redS[rl][1] + redS[rl][2] + redS[rl][3];
            float sq0  = redQ[rl][0] + redQ[rl][1] + redQ[rl][2] + redQ[rl][3];
            float sum1 = redS[rl+8][0] + redS[rl+8][1] + redS[rl+8][2] + redS[rl+8][3];
            float sq1  = redQ[rl+8][0] + redQ[rl+8][1] + redQ[rl+8][2] + redQ[rl+8][3];
            float mean0 = sum0 * (1.f/128.f);
            float mean1 = sum1 * (1.f/128.f);
            float rstd0 = rsqrtf(sq0 * (1.f/128.f) - mean0*mean0 + 1e-5f);
            float rstd1 = rsqrtf(sq1 * (1.f/128.f) - mean1*mean1 + 1e-5f);
#pragma unroll
            for (int nf = 0; nf < 4; nf++) {
                const int c = wn * 32 + nf * 8 + tq * 2;
                float y0 = (acc[mf][nf][0] - mean0) * rstd0 * lng_s[c]   + lnb_s[c];
                float y1 = (acc[mf][nf][1] - mean0) * rstd0 * lng_s[c+1] + lnb_s[c+1];
                float y2 = (acc[mf][nf][2] - mean1) * rstd1 * lng_s[c]   + lnb_s[c];
                float y3 = (acc[mf][nf][3] - mean1) * rstd1 * lng_s[c+1] + lnb_s[c+1];
                *reinterpret_cast<float2*>(outF + (size_t)m0 * 128 + c) = make_float2(y0, y1);
                *reinterpret_cast<float2*>(outF + (size_t)m1 * 128 + c) = make_float2(y2, y3);
                *reinterpret_cast<uint32_t*>(outB + (size_t)m0 * 128 + c) = packbf2(y0, y1);
                *reinterpret_cast<uint32_t*>(outB + (size_t)m1 * 128 + c) = packbf2(y2, y3);
            }
        }
    } else {
#pragma unroll
        for (int mf = 0; mf < 4; mf++) {
            const int m0 = row0 + wm * 64 + mf * 16 + g;
            const int m1 = m0 + 8;
#pragma unroll
            for (int nf = 0; nf < 4; nf++) {
                const int c = wn * 32 + nf * 8 + tq * 2;
                float v0 = acc[mf][nf][0] + bias_s[c];
                float v1 = acc[mf][nf][1] + bias_s[c + 1];
                float v2 = acc[mf][nf][2] + bias_s[c];
                float v3 = acc[mf][nf][3] + bias_s[c + 1];
                if (EPI == 0) {
                    __nv_bfloat16* dst = (blockIdx.x == 0) ? qo : ((blockIdx.x == 1) ? ko : vo);
                    if (blockIdx.x == 0) { v0 *= QSCALE; v1 *= QSCALE; v2 *= QSCALE; v3 *= QSCALE; }
                    const int hh = c >> 5, dd = c & 31;
                    int b0i = m0 >> 11, s0i = m0 & 2047;
                    int b1i = m1 >> 11, s1i = m1 & 2047;
                    *reinterpret_cast<uint32_t*>(dst + ((size_t)(b0i * H_ + hh) * S_ + s0i) * DH_ + dd) = packbf2(v0, v1);
                    *reinterpret_cast<uint32_t*>(dst + ((size_t)(b1i * H_ + hh) * S_ + s1i) * DH_ + dd) = packbf2(v2, v3);
                } else {
                    *reinterpret_cast<uint32_t*>(outB + (size_t)m0 * Nstride + n0 + c) =
                        packbf2(fmaxf(v0, 0.f), fmaxf(v1, 0.f));
                    *reinterpret_cast<uint32_t*>(outB + (size_t)m1 * Nstride + n0 + c) =
                        packbf2(fmaxf(v2, 0.f), fmaxf(v3, 0.f));
                }
            }
        }
    }
}

// ======================= pipelined MMA flash attention (3-stage) =======================
// CTA: (bh, 128 queries). 8 warps x 16 queries; 64-key tiles; Q pre-scaled -> ex2.
// smem (dynamic): Qs@0 (10240), stage s: K@10240+s*10240, V@15360+s*10240 (total 40960)
#define AT_SMEM 40960
#define NKV (S_ >> 6)
__global__ __launch_bounds__(256)
void attn_kernel(const __nv_bfloat16* __restrict__ q, const __nv_bfloat16* __restrict__ k,
                 const __nv_bfloat16* __restrict__ v, __nv_bfloat16* __restrict__ out)
{
    extern __shared__ char smx[];
    const uint32_t sbase = cvta_s(smx);
    const uint32_t sQ = sbase;

    const int t    = threadIdx.x;
    const int wid  = t >> 5;
    const int lane = t & 31;
    const int g    = lane >> 2;
    const int tq   = lane & 3;
    const int bh   = blockIdx.y, b = bh >> 2, h = bh & 3;
    const int q0   = blockIdx.x * 128;

    auto sK = [&](int s) -> uint32_t { return sbase + 10240 + s * 10240; };
    auto sV = [&](int s) -> uint32_t { return sbase + 15360 + s * 10240; };

    auto load_kv = [&](int tile, int stg) {
        const int j0 = tile << 6;
        int r = t >> 2, qq = t & 3;
        cp16(sK(stg) + r * (TST*2) + qq * 16, &k[((size_t)bh * S_ + j0 + r) * DH_ + qq * 8]);
        cp16(sV(stg) + r * (TST*2) + qq * 16, &v[((size_t)bh * S_ + j0 + r) * DH_ + qq * 8]);
    };

    // prologue: group0 = Q + KV0, group1 = KV1
#pragma unroll
    for (int i = 0; i < 2; i++) {
        int id = t + (i << 8);
        int r = id >> 2, qq = id & 3;
        cp16(sQ + r * (TST*2) + qq * 16, &q[((size_t)bh * S_ + q0 + r) * DH_ + qq * 8]);
    }
    load_kv(0, 0);
    CP_COMMIT();
    load_kv(1, 1);
    CP_COMMIT();

    float o[4][4];
    float lg = 0.f, lg8 = 0.f;
#pragma unroll
    for (int nf = 0; nf < 4; nf++)
#pragma unroll
        for (int e = 0; e < 4; e++) o[nf][e] = 0.f;

    uint32_t af2[2][4];

    const int aRow = wid * 16 + (lane & 15);
    const int aColX = (lane >> 4) * 8;
    const int bRow = (lane & 7) + ((lane >> 4) << 3);
    const int bColX = ((lane >> 3) & 1) * 8;
    const int vRow = (lane & 7) + (((lane >> 3) & 1) << 3);
    const int vColX = (lane >> 4) * 8;

    for (int it = 0; it < NKV; it++) {
        const int stg = it % 3;
        if (it < NKV - 1) CP_WAIT(1); else CP_WAIT(0);
        __syncthreads();
        if (it + 2 < NKV) { load_kv(it + 2, (it + 2) % 3); CP_COMMIT(); }

        if (it == 0) {
#pragma unroll
            for (int ks = 0; ks < 2; ks++)
                ldm_x4(af2[ks], sQ + (aRow * TST + ks * 16 + aColX) * 2);
        }

        // scores = Q @ K^T
        float sc[8][4];
#pragma unroll
        for (int nf = 0; nf < 8; nf++)
#pragma unroll
            for (int e = 0; e < 4; e++) sc[nf][e] = 0.f;
#pragma unroll
        for (int ks = 0; ks < 2; ks++) {
            const int kk = ks << 4;
#pragma unroll
            for (int pp = 0; pp < 4; pp++) {
                uint32_t r4[4];
                ldm_x4(r4, sK(stg) + ((pp * 16 + bRow) * TST + kk + bColX) * 2);
                uint32_t b0[2] = { r4[0], r4[1] }, b1[2] = { r4[2], r4[3] };
                mma16816(sc[pp*2],   af2[ks], b0);
                mma16816(sc[pp*2+1], af2[ks], b1);
            }
        }

        // p = ex2(s) (Q pre-scaled); accumulate l; pack PV A-fragments
        uint32_t pb[8][2];
#pragma unroll
        for (int nf = 0; nf < 8; nf++) {
            float p0 = ex2f(sc[nf][0]);
            float p1 = ex2f(sc[nf][1]);
            float p2 = ex2f(sc[nf][2]);
            float p3 = ex2f(sc[nf][3]);
            lg  += p0 + p1;
            lg8 += p2 + p3;
            pb[nf][0] = packbf2(p0, p1);
            pb[nf][1] = packbf2(p2, p3);
        }

        // O += P @ V
#pragma unroll
        for (int kf = 0; kf < 4; kf++) {
            uint32_t a4[4] = { pb[2*kf][0], pb[2*kf][1], pb[2*kf+1][0], pb[2*kf+1][1] };
#pragma unroll
            for (int pp = 0; pp < 2; pp++) {
                uint32_t r4[4];
                ldm_x4t(r4, sV(stg) + ((kf * 16 + vRow) * TST + pp * 16 + vColX) * 2);
                uint32_t b0[2] = { r4[0], r4[1] }, b1[2] = { r4[2], r4[3] };
                mma16816(o[pp*2],   a4, b0);
                mma16816(o[pp*2+1], a4, b1);
            }
        }
    }

    lg  += __shfl_xor_sync(0xffffffffu, lg, 1);
    lg  += __shfl_xor_sync(0xffffffffu, lg, 2);
    lg8 += __shfl_xor_sync(0xffffffffu, lg8, 1);
    lg8 += __shfl_xor_sync(0xffffffffu, lg8, 2);
    const float inv0 = 1.f / lg;
    const float inv1 = 1.f / lg8;

    const int r0 = q0 + wid * 16 + g;
    const int r1 = r0 + 8;
#pragma unroll
    for (int nf = 0; nf < 4; nf++) {
        const int dd = nf * 8 + tq * 2;
        *reinterpret_cast<uint32_t*>(out + ((size_t)(b * S_ + r0)) * D_ + h * DH_ + dd) =
            packbf2(o[nf][0] * inv0, o[nf][1] * inv0);
        *reinterpret_cast<uint32_t*>(out + ((size_t)(b * S_ + r1)) * D_ + h * DH_ + dd) =
            packbf2(o[nf][2] * inv1, o[nf][3] * inv1);
    }
}

// ======================= Head: FC -> softmax -> rebalance =======================
__global__ __launch_bounds__(512)
void head_kernel(const float* __restrict__ hbuf, const float* __restrict__ fcw,
                 const float* __restrict__ fcb, float* __restrict__ out)
{
    __shared__ float logits[B_][OUT_];
    const int t = threadIdx.x;
    if (t < B_ * OUT_) {
        int b = t / OUT_;
        int o = t % OUT_;
        const float* hr = hbuf + ((size_t)(b * S_ + (S_ - 1))) * D_;
        float acc = fcb[o];
        for (int d = 0; d < D_; d++) acc += hr[d] * fcw[o * D_ + d];
        logits[b][o] = acc;
    }
    __syncthreads();
    if (t < B_) {
        const float UB = 0.3f, LB = 0.0f;
        float wv[OUT_], old[OUT_], wc[OUT_], res[OUT_];
        float mx = -1e30f;
        for (int o = 0; o < OUT_; o++) mx = fmaxf(mx, logits[t][o]);
        float sum = 0.f;
        for (int o = 0; o < OUT_; o++) { wv[o] = expf(logits[t][o] - mx); sum += wv[o]; }
        float inv = 1.f / sum;
        for (int o = 0; o < OUT_; o++) wv[o] *= inv;
        bool done = false;
        for (int o = 0; o < OUT_; o++) {
            old[o] = wv[o];
            wc[o]  = fminf(fmaxf(wv[o], LB), UB);
            res[o] = wv[o];
        }
        for (int it = 0; it < 16; it++) {
            float leftover = 0.f;
            for (int o = 0; o < OUT_; o++) leftover += old[o] - wc[o];
            float denom = 0.f;
            float noms[OUT_];
            for (int o = 0; o < OUT_; o++) {
                noms[o] = (wc[o] != UB) ? wc[o] : 0.f;
                denom += noms[o];
            }
            if (denom == 0.f) denom = 1.f;
            float cand[OUT_];
            bool any = false;
            for (int o = 0; o < OUT_; o++) {
                cand[o] = wc[o] + leftover * noms[o] / denom;
                if (cand[o] > UB) any = true;
            }
            if (!done)
                for (int o = 0; o < OUT_; o++) res[o] = cand[o];
            done = done || !any;
            if (!done) {
                for (int o = 0; o < OUT_; o++) {
                    old[o] = cand[o];
                    wc[o]  = fminf(fmaxf(cand[o], LB), UB);
                }
            }
        }
        for (int o = 0; o < OUT_; o++) out[t * OUT_ + o] = res[o];
    }
}

// ======================= launch =======================
extern "C" void kernel_launch(void* const* d_in, const int* in_sizes, int n_in,
                              void* d_out, int out_size)
{
    const float* x   = (const float*)d_in[0];
    const float* ipw = (const float*)d_in[1];
    const float* ipb = (const float*)d_in[2];
    const float* ow  = (const float*)d_in[3];
    const float* ob  = (const float*)d_in[4];
    const float* l1g = (const float*)d_in[5];
    const float* l1b = (const float*)d_in[6];
    const float* f1w = (const float*)d_in[7];
    const float* f1b = (const float*)d_in[8];
    const float* f2w = (const float*)d_in[9];
    const float* f2b = (const float*)d_in[10];
    const float* l2g = (const float*)d_in[11];
    const float* l2b = (const float*)d_in[12];
    const float* fcw = (const float*)d_in[13];
    const float* fcb = (const float*)d_in[14];

    __nv_bfloat16 *qb, *kb, *vb, *attnb, *hb, *ffb, *wip, *wout, *wf1, *wf2;
    float *h;
    cudaGetSymbolAddress((void**)&qb,    g_qb);
    cudaGetSymbolAddress((void**)&kb,    g_kb);
    cudaGetSymbolAddress((void**)&vb,    g_vb);
    cudaGetSymbolAddress((void**)&attnb, g_attnb);
    cudaGetSymbolAddress((void**)&hb,    g_hb);
    cudaGetSymbolAddress((void**)&h,     g_h);
    cudaGetSymbolAddress((void**)&ffb,   g_ffb);
    cudaGetSymbolAddress((void**)&wip,   g_wip);
    cudaGetSymbolAddress((void**)&wout,  g_wout);
    cudaGetSymbolAddress((void**)&wf1,   g_wf1);
    cudaGetSymbolAddress((void**)&wf2,   g_wf2);

    cudaFuncSetAttribute(mm_kernel<0>, cudaFuncAttributeMaxDynamicSharedMemorySize, MM_SMEM);
    cudaFuncSetAttribute(mm_kernel<1>, cudaFuncAttributeMaxDynamicSharedMemorySize, MM_SMEM);
    cudaFuncSetAttribute(mm_kernel<2>, cudaFuncAttributeMaxDynamicSharedMemorySize, MM_SMEM);
    cudaFuncSetAttribute(attn_kernel,  cudaFuncAttributeMaxDynamicSharedMemorySize, AT_SMEM);

    // conversions interleaved so attention is an early launch index (profiling)
    cvt_kernel<<<(L_*3*D_*D_)/1024, 256>>>(ipw, wip, L_*3*D_*D_);   // launch 0
    cvt_kernel<<<(M_*D_)/1024,      256>>>(x,   hb,  M_*D_);        // launch 1

    for (int l = 0; l < L_; l++) {
        const float* hinF = (l == 0) ? x : h;

        // QKV projection -> q/k/v bf16 [b,h,s,32] (q pre-scaled)
        mm_kernel<0><<<dim3(3, M_/128), 256, MM_SMEM>>>(
            hb, wip + (size_t)l*3*D_*D_, ipb + (size_t)l*3*D_,
            nullptr, nullptr, nullptr, nullptr, nullptr, qb, kb, vb, 3*D_, D_);

        // flash attention
        attn_kernel<<<dim3(S_/128, B_*H_), 256, AT_SMEM>>>(qb, kb, vb, attnb);

        if (l == 0) cvt_kernel<<<(L_*D_*D_)/1024, 256>>>(ow, wout, L_*D_*D_);

        // out projection + residual + LN1 -> h, hb
        mm_kernel<2><<<dim3(1, M_/128), 256, MM_SMEM>>>(
            attnb, wout + (size_t)l*D_*D_, ob + (size_t)l*D_,
            hinF, l1g + (size_t)l*D_, l1b + (size_t)l*D_,
            h, hb, nullptr, nullptr, nullptr, D_, D_);

        if (l == 0) cvt_kernel<<<(L_*FF_*D_)/1024, 256>>>(f1w, wf1, L_*FF_*D_);

        // FF1 + relu -> ffb (bf16)
        mm_kernel<1><<<dim3(FF_/128, M_/128), 256, MM_SMEM>>>(
            hb, wf1 + (size_t)l*FF_*D_, f1b + (size_t)l*FF_,
            nullptr, nullptr, nullptr, nullptr, ffb, nullptr, nullptr, nullptr, FF_, D_);

        if (l == 0) cvt_kernel<<<(L_*D_*FF_)/1024, 256>>>(f2w, wf2, L_*D_*FF_);

        // FF2 + residual(h) + LN2 -> h, hb
        mm_kernel<2><<<dim3(1, M_/128), 256, MM_SMEM>>>(
            ffb, wf2 + (size_t)l*D_*FF_, f2b + (size_t)l*D_,
            h, l2g + (size_t)l*D_, l2b + (size_t)l*D_,
            h, hb, nullptr, nullptr, nullptr, D_, FF_);
    }

    head_kernel<<<1, 512>>>(h, fcw, fcb, (float*)d_out);
}